// round 15
// baseline (speedup 1.0000x reference)
#include <cuda_runtime.h>
#include <cuda_fp16.h>
#include <cstdint>
#include <math.h>

#define NB 4
#define LQ 2048
#define CH 1024
#define NHD 8
#define HD 128
#define NL (NB * LQ)
#define NHT (NB * NHD)
#define KVSPLIT 8
#define EPS_ATTN 1e-6f
#define EPS_LN 1e-5f

// fp16 GEMM tiles: CTA 256(M) x 128(N), 32 words (64 halves) K per stage, 2 stages, 1 CTA/SM
#define BSTR 136
#define ASTR2 36
#define A2_WORDS (256 * ASTR2)            // 9216
#define B2_WORDS (32 * BSTR)              // 4352
#define STG2_WORDS (A2_WORDS + B2_WORDS)  // 13568
#define GEMM_SMEM2 (2 * STG2_WORDS * 4)   // 108544

// fp16 attention tiles
#define KH_ASTR 17     // Kt/Qs stride (words)
#define VSTR 137       // attn_kv V stride (scalar STS only)
#define BCP_STR 136    // attn_out B stride (cp.async 16B-aligned rows)

// ---------------- scratch (256B-aligned) ----------------
__device__ __align__(256) float g_ctx[NL * CH];
__device__ __align__(256) float g_msg[NL * CH];
__device__ __align__(256) float g_x[NL * CH];
__device__ __align__(256) float g_y[NL * CH];
__device__ __align__(256) __half g_ctxh[NL * CH];
__device__ __align__(256) __half g_xh[NL * CH];
__device__ __align__(256) __half g_yh[NL * CH];
__device__ __align__(256) __half g_attnh[NL * CH];
__device__ __align__(256) __half g_deph[NL * CH];
__device__ __align__(256) __half g_hh[NL * 2 * CH];
__device__ __align__(256) __half g_qkvh[NL * 3 * CH];
__device__ __align__(256) uint32_t g_wt[12 * 1024 * 1024];
__device__ __align__(256) float g_kvpart[KVSPLIT * NHT * HD * HD];
__device__ __align__(256) uint32_t g_kvh[NHT * (HD / 2) * HD];
__device__ __align__(256) float g_kspart[KVSPLIT * NHT * HD];
__device__ __align__(256) float g_ksum[NHT * HD];

__device__ __forceinline__ float fmap(float x) { return x > 0.0f ? x + 1.0f : expf(x); }

__device__ __forceinline__ void cp16(uint32_t saddr, const void* g) {
    asm volatile("cp.async.cg.shared.global [%0], [%1], 16;" :: "r"(saddr), "l"(g));
}

__device__ __forceinline__ uint32_t smem_u32(const void* p) {
    uint32_t a;
    asm("{ .reg .u64 t; cvta.to.shared.u64 t, %1; cvt.u32.u64 %0, t; }" : "=r"(a) : "l"(p));
    return a;
}

__device__ __forceinline__ void mma_f16(float* d,
                                        uint32_t a0, uint32_t a1, uint32_t a2, uint32_t a3,
                                        uint32_t b0, uint32_t b1) {
    asm volatile(
        "mma.sync.aligned.m16n8k16.row.col.f32.f16.f16.f32 "
        "{%0,%1,%2,%3}, {%4,%5,%6,%7}, {%8,%9}, {%0,%1,%2,%3};"
        : "+f"(d[0]), "+f"(d[1]), "+f"(d[2]), "+f"(d[3])
        : "r"(a0), "r"(a1), "r"(a2), "r"(a3), "r"(b0), "r"(b1));
}

// ---------------- weight pack: fp32 [K][N] -> half2 words [K/2][ostride] ----------------
struct PKArgs {
    const float* src[17];
    uint32_t* dst[17];
    int total[17];
    int lgN[17];
    int ostride[17];
    int colofs[17];
};
__global__ void pack_w(PKArgs a) {
    const int seg = blockIdx.y;
    const float* __restrict__ s = a.src[seg];
    uint32_t* __restrict__ d = a.dst[seg];
    const int total = a.total[seg];
    const int lg = a.lgN[seg];
    const int Nm = (1 << lg) - 1;
    const int ostr = a.ostride[seg];
    const int co = a.colofs[seg];
    int idx = blockIdx.x * blockDim.x + threadIdx.x;
    int stride = gridDim.x * blockDim.x;
    for (int i = idx; i < total; i += stride) {
        int n = i & Nm;
        int k2 = i >> lg;
        size_t slo = ((size_t)k2 << (lg + 1)) + n;
        float lo = s[slo];
        float hi = s[slo + (1 << lg)];
        __half2 h = __floats2half2_rn(lo, hi);
        d[(size_t)k2 * ostr + co + n] = *(uint32_t*)&h;
    }
}

// ---------------- fp16 GEMM: CTA 256x128, 256 thr, 8 warps (4M x 2N of 64x64) -------------
// OUTM: 0 = fp32 out, 2 = fp16 out
template <bool RELU, int OUTM>
__global__ __launch_bounds__(256, 1) void gemm_h(
    const uint32_t* __restrict__ Aw, const uint32_t* __restrict__ Bw, void* __restrict__ Cout,
    int M, int Kw, int Nn) {
    extern __shared__ uint32_t sm[];
    const uint32_t smaddr = smem_u32(sm);
    const int tid = threadIdx.x;
    const int wid = tid >> 5, lane = tid & 31;
    const int bm = blockIdx.y * 256;
    const int bn = blockIdx.x * 128;
    const int wm = (wid & 3) * 64;
    const int wn = (wid >> 2) * 64;
    const int r = lane >> 2, cq = lane & 3;

    float acc[4][8][4];
#pragma unroll
    for (int i = 0; i < 4; i++)
#pragma unroll
        for (int j = 0; j < 8; j++)
#pragma unroll
            for (int c = 0; c < 4; c++) acc[i][j][c] = 0.0f;

    const int KT = Kw / 32;

    auto issue = [&](int s, int kt) {
        const uint32_t sbA = smaddr + s * (STG2_WORDS * 4);
        const uint32_t* Ag = Aw + (size_t)bm * Kw + (size_t)kt * 32;
#pragma unroll
        for (int i = 0; i < 8; i++) {
            int idx = tid + 256 * i;
            int row = idx >> 3, c4 = (idx & 7) * 4;
            cp16(sbA + (row * ASTR2 + c4) * 4, Ag + (size_t)row * Kw + c4);
        }
        const uint32_t sbB = sbA + A2_WORDS * 4;
        const uint32_t* Bg = Bw + (size_t)(kt * 32) * Nn + bn;
#pragma unroll
        for (int i = 0; i < 4; i++) {
            int idx = tid + 256 * i;
            int kk = idx >> 5, n4 = (idx & 31) * 4;
            cp16(sbB + (kk * BSTR + n4) * 4, Bg + (size_t)kk * Nn + n4);
        }
        asm volatile("cp.async.commit_group;" ::: "memory");
    };

    issue(0, 0);

    for (int kt = 0; kt < KT; kt++) {
        const int buf = kt & 1;
        asm volatile("cp.async.wait_group 0;" ::: "memory");
        __syncthreads();
        if (kt + 1 < KT) issue(buf ^ 1, kt + 1);

        const uint32_t* Asb = sm + buf * STG2_WORDS;
        const uint32_t* Bsb = Asb + A2_WORDS;
#pragma unroll
        for (int s = 0; s < 4; s++) {
            uint32_t af[4][4];
#pragma unroll
            for (int i = 0; i < 4; i++) {
                const int arow = wm + 16 * i + r;
                const int kc = 8 * s + cq;
                af[i][0] = Asb[arow * ASTR2 + kc];
                af[i][1] = Asb[(arow + 8) * ASTR2 + kc];
                af[i][2] = Asb[arow * ASTR2 + kc + 4];
                af[i][3] = Asb[(arow + 8) * ASTR2 + kc + 4];
            }
            uint32_t bf[8][2];
#pragma unroll
            for (int j = 0; j < 8; j++) {
                const int ncol = wn + 8 * j + r;
                bf[j][0] = Bsb[(8 * s + cq) * BSTR + ncol];
                bf[j][1] = Bsb[(8 * s + cq + 4) * BSTR + ncol];
            }
#pragma unroll
            for (int i = 0; i < 4; i++)
#pragma unroll
                for (int j = 0; j < 8; j++)
                    mma_f16(acc[i][j], af[i][0], af[i][1], af[i][2], af[i][3],
                            bf[j][0], bf[j][1]);
        }
    }

#pragma unroll
    for (int i = 0; i < 4; i++) {
        const int row0 = bm + wm + 16 * i + r;
#pragma unroll
        for (int j = 0; j < 8; j++) {
            const int col = bn + wn + 8 * j + 2 * cq;
            float v[4] = {acc[i][j][0], acc[i][j][1], acc[i][j][2], acc[i][j][3]};
            if (RELU) {
#pragma unroll
                for (int c = 0; c < 4; c++) v[c] = fmaxf(v[c], 0.f);
            }
            if (OUTM == 2) {
                __half* Ch = (__half*)Cout;
                __half2 h0 = __floats2half2_rn(v[0], v[1]);
                __half2 h1 = __floats2half2_rn(v[2], v[3]);
                *(__half2*)(Ch + (size_t)row0 * Nn + col) = h0;
                *(__half2*)(Ch + (size_t)(row0 + 8) * Nn + col) = h1;
            } else {
                float* Cf = (float*)Cout;
                float2 v0, v1;
                v0.x = v[0]; v0.y = v[1]; v1.x = v[2]; v1.y = v[3];
                *(float2*)(Cf + (size_t)row0 * Nn + col) = v0;
                *(float2*)(Cf + (size_t)(row0 + 8) * Nn + col) = v1;
            }
        }
    }
}

// ---------------- elementwise add (fp32 out + fp16 copy) ----------------
__global__ void add_kernel(const float* __restrict__ a, const float* __restrict__ b,
                           float* __restrict__ o, __half* __restrict__ oh, int n4) {
    int idx = blockIdx.x * blockDim.x + threadIdx.x;
    int stride = gridDim.x * blockDim.x;
    const float4* a4 = (const float4*)a;
    const float4* b4 = (const float4*)b;
    float4* o4 = (float4*)o;
    for (int i = idx; i < n4; i += stride) {
        float4 x = a4[i], y = b4[i];
        x.x += y.x; x.y += y.y; x.z += y.z; x.w += y.w;
        o4[i] = x;
        __half2 h0 = __floats2half2_rn(x.x, x.y);
        __half2 h1 = __floats2half2_rn(x.z, x.w);
        uint2 u;
        u.x = *(uint32_t*)&h0; u.y = *(uint32_t*)&h1;
        *(uint2*)(oh + (size_t)i * 4) = u;
    }
}

// ---------------- fp16 attn KV: KV = fmap(K)^T @ V over L-slice + ksum ----------------
// 1 barrier per k-tile (sts(buf^1) races only with compute(buf^1)@kt-1, ordered by prior sync)
__global__ __launch_bounds__(128) void attn_kv_h(
    const __half* __restrict__ Kg, const __half* __restrict__ Vg, int ld,
    float* __restrict__ kvpart, float* __restrict__ kspart) {
    __shared__ uint32_t Kt[2][128 * KH_ASTR];  // [d][w]
    __shared__ uint32_t Vs[2][16 * VSTR];      // [w][v]
    __shared__ float ksp[16][129];

    const int nh = blockIdx.x;
    const int split = blockIdx.y;
    const int n = nh >> 3, h = nh & 7;
    const int lbase = split * (LQ / KVSPLIT);
    const int tid = threadIdx.x;
    const int wid = tid >> 5, lane = tid & 31;
    const int wm = (wid & 1) * 64;
    const int wn = (wid >> 1) * 64;
    const int r = lane >> 2, cq = lane & 3;

    const int w = tid & 15;
    const int db = (tid >> 4) * 16;
    const size_t base = ((size_t)(n * LQ + lbase)) * ld + h * HD;

    float acc[4][8][4];
#pragma unroll
    for (int i = 0; i < 4; i++)
#pragma unroll
        for (int j = 0; j < 8; j++)
#pragma unroll
            for (int c = 0; c < 4; c++) acc[i][j][c] = 0.0f;
    float kacc[16];
#pragma unroll
    for (int i = 0; i < 16; i++) kacc[i] = 0.0f;

    uint4 kr[4], vr[4];
    const int KT = (LQ / KVSPLIT) / 32;   // 8

    auto ldg = [&](int kt) {
        const __half* kp = Kg + base + (size_t)(kt * 32 + 2 * w) * ld + db;
        kr[0] = *(const uint4*)kp;
        kr[1] = *(const uint4*)(kp + 8);
        kr[2] = *(const uint4*)(kp + ld);
        kr[3] = *(const uint4*)(kp + ld + 8);
        const __half* vp = Vg + base + (size_t)(kt * 32 + 2 * w) * ld + db;
        vr[0] = *(const uint4*)vp;
        vr[1] = *(const uint4*)(vp + 8);
        vr[2] = *(const uint4*)(vp + ld);
        vr[3] = *(const uint4*)(vp + ld + 8);
    };
    auto sts = [&](int buf) {
        const __half* kh = (const __half*)kr;
        const __half* vh = (const __half*)vr;
#pragma unroll
        for (int i = 0; i < 16; i++) {
            float lo = fmap(__half2float(kh[i]));
            float hi = fmap(__half2float(kh[16 + i]));
            __half2 p = __floats2half2_rn(lo, hi);
            float2 pr = __half22float2(p);
            kacc[i] += pr.x + pr.y;
            Kt[buf][(db + i) * KH_ASTR + w] = *(uint32_t*)&p;
            __half2 pv = __halves2half2(vh[i], vh[16 + i]);
            Vs[buf][w * VSTR + db + i] = *(uint32_t*)&pv;
        }
    };

    ldg(0);
    sts(0);
    __syncthreads();

    for (int kt = 0; kt < KT; kt++) {
        const int buf = kt & 1;
        if (kt + 1 < KT) ldg(kt + 1);

        const uint32_t* Asb = Kt[buf];
        const uint32_t* Bsb = Vs[buf];
#pragma unroll
        for (int s = 0; s < 2; s++) {
            uint32_t af[4][4];
#pragma unroll
            for (int i = 0; i < 4; i++) {
                const int arow = wm + 16 * i + r;
                const int kc = 8 * s + cq;
                af[i][0] = Asb[arow * KH_ASTR + kc];
                af[i][1] = Asb[(arow + 8) * KH_ASTR + kc];
                af[i][2] = Asb[arow * KH_ASTR + kc + 4];
                af[i][3] = Asb[(arow + 8) * KH_ASTR + kc + 4];
            }
            uint32_t bf[8][2];
#pragma unroll
            for (int j = 0; j < 8; j++) {
                const int ncol = wn + 8 * j + r;
                bf[j][0] = Bsb[(8 * s + cq) * VSTR + ncol];
                bf[j][1] = Bsb[(8 * s + cq + 4) * VSTR + ncol];
            }
#pragma unroll
            for (int i = 0; i < 4; i++)
#pragma unroll
                for (int j = 0; j < 8; j++)
                    mma_f16(acc[i][j], af[i][0], af[i][1], af[i][2], af[i][3],
                            bf[j][0], bf[j][1]);
        }
        if (kt + 1 < KT) sts(buf ^ 1);
        __syncthreads();
    }

    float* o = kvpart + (((size_t)(split * NHT + nh)) << 14);
#pragma unroll
    for (int i = 0; i < 4; i++) {
        const int row0 = wm + 16 * i + r;
#pragma unroll
        for (int j = 0; j < 8; j++) {
            const int col = wn + 8 * j + 2 * cq;
            float2 v0, v1;
            v0.x = acc[i][j][0]; v0.y = acc[i][j][1];
            v1.x = acc[i][j][2]; v1.y = acc[i][j][3];
            *(float2*)(o + (size_t)row0 * HD + col) = v0;
            *(float2*)(o + (size_t)(row0 + 8) * HD + col) = v1;
        }
    }

#pragma unroll
    for (int i = 0; i < 16; i++) ksp[w][db + i] = kacc[i];
    __syncthreads();
    {
        int d = tid;
        float s = 0.0f;
#pragma unroll
        for (int j = 0; j < 16; j++) s += ksp[j][d];
        kspart[(split * NHT + nh) * HD + d] = s;
    }
}

// ---------------- KV reduce -> packed half2 words [d/2][v] ----------------
__global__ void kv_reduce_h(const float* __restrict__ part, uint32_t* __restrict__ kvh) {
    int idx = blockIdx.x * 256 + threadIdx.x;
    if (idx < NHT * (HD / 2) * HD) {
        int nh = idx >> 13;
        int d2 = (idx >> 7) & 63;
        int v = idx & 127;
        float lo = 0.0f, hi = 0.0f;
#pragma unroll
        for (int sp = 0; sp < KVSPLIT; sp++) {
            const float* p = part + (((size_t)(sp * NHT + nh)) << 14);
            lo += p[(2 * d2) * HD + v];
            hi += p[(2 * d2 + 1) * HD + v];
        }
        __half2 h = __floats2half2_rn(lo, hi);
        kvh[idx] = *(uint32_t*)&h;
    }
}

__global__ void ks_reduce_kernel(const float* __restrict__ part, float* __restrict__ ks) {
    int idx = blockIdx.x * 128 + threadIdx.x;
    int nh = idx >> 7, d = idx & 127;
    float s = 0.0f;
#pragma unroll
    for (int sp = 0; sp < KVSPLIT; sp++)
        s += part[(sp * NHT + nh) * HD + d];
    ks[idx] = s;
}

// ---------------- fp16 attn out: O = fmap(Q) @ KV * Z ----------------
__global__ __launch_bounds__(128) void attn_out_h(
    const __half* __restrict__ Qg, int ldq, const uint32_t* __restrict__ KVh,
    const float* __restrict__ Ksum, __half* __restrict__ Og) {
    __shared__ uint32_t Qs[2][128 * KH_ASTR];
    __shared__ uint32_t Bs[2][16 * BCP_STR];
    __shared__ float kss[HD];
    __shared__ float qks[128];
    const uint32_t BsAddr = smem_u32(Bs);

    const int nh = blockIdx.y;
    const int n = nh >> 3, h = nh & 7;
    const int l0 = blockIdx.x * 128;
    const int tid = threadIdx.x;
    const int wid = tid >> 5, lane = tid & 31;
    const int wm = (wid & 1) * 64;
    const int wn = (wid >> 1) * 64;
    const int r = lane >> 2, cq = lane & 3;

    kss[tid] = Ksum[nh * HD + tid];

    const size_t qbase = ((size_t)(n * LQ + l0)) * ldq + h * HD;
    const uint32_t* kvb = KVh + ((size_t)nh << 13);

    const int qrow0 = tid >> 2;
    const int qw4 = (tid & 3) * 4;

    float acc[4][8][4];
#pragma unroll
    for (int i = 0; i < 4; i++)
#pragma unroll
        for (int j = 0; j < 8; j++)
#pragma unroll
            for (int c = 0; c < 4; c++) acc[i][j][c] = 0.0f;
    float qkp[4] = {0.f, 0.f, 0.f, 0.f};

    uint4 qr[4];
    const int KT = HD / 32;   // 4

    auto ldgQ = [&](int kt) {
#pragma unroll
        for (int i = 0; i < 4; i++)
            qr[i] = *(const uint4*)(Qg + qbase + (size_t)(qrow0 + 32 * i) * ldq + kt * 32 + qw4 * 2);
    };
    auto stsQ = [&](int buf, int kt) {
#pragma unroll
        for (int i = 0; i < 4; i++) {
            const __half* qh = (const __half*)&qr[i];
#pragma unroll
            for (int j = 0; j < 4; j++) {
                float lo = fmap(__half2float(qh[2 * j]));
                float hi = fmap(__half2float(qh[2 * j + 1]));
                __half2 p = __floats2half2_rn(lo, hi);
                float2 pr = __half22float2(p);
                const int dc = kt * 32 + (qw4 + j) * 2;
                qkp[i] += pr.x * kss[dc] + pr.y * kss[dc + 1];
                Qs[buf][(qrow0 + 32 * i) * KH_ASTR + qw4 + j] = *(uint32_t*)&p;
            }
        }
    };
    auto cpB = [&](int buf, int kt) {
#pragma unroll
        for (int i = 0; i < 4; i++) {
            int idx = tid + 128 * i;
            int kk = idx >> 5, v4 = (idx & 31) * 4;
            cp16(BsAddr + (buf * (16 * BCP_STR) + kk * BCP_STR + v4) * 4,
                 kvb + (size_t)(kt * 16 + kk) * HD + v4);
        }
        asm volatile("cp.async.commit_group;" ::: "memory");
    };

    ldgQ(0);
    cpB(0, 0);
    __syncthreads();   // kss visible to all warps BEFORE first stsQ reads it
    stsQ(0, 0);
    asm volatile("cp.async.wait_group 0;" ::: "memory");
    __syncthreads();

    for (int kt = 0; kt < KT; kt++) {
        const int buf = kt & 1;
        if (kt + 1 < KT) {
            cpB(buf ^ 1, kt + 1);
            ldgQ(kt + 1);
        }
        const uint32_t* Asb = Qs[buf];
        const uint32_t* Bsb = Bs[buf];
#pragma unroll
        for (int s = 0; s < 2; s++) {
            uint32_t af[4][4];
#pragma unroll
            for (int i = 0; i < 4; i++) {
                const int arow = wm + 16 * i + r;
                const int kc = 8 * s + cq;
                af[i][0] = Asb[arow * KH_ASTR + kc];
                af[i][1] = Asb[(arow + 8) * KH_ASTR + kc];
                af[i][2] = Asb[arow * KH_ASTR + kc + 4];
                af[i][3] = Asb[(arow + 8) * KH_ASTR + kc + 4];
            }
            uint32_t bf[8][2];
#pragma unroll
            for (int j = 0; j < 8; j++) {
                const int ncol = wn + 8 * j + r;
                bf[j][0] = Bsb[(8 * s + cq) * BCP_STR + ncol];
                bf[j][1] = Bsb[(8 * s + cq + 4) * BCP_STR + ncol];
            }
#pragma unroll
            for (int i = 0; i < 4; i++)
#pragma unroll
                for (int j = 0; j < 8; j++)
                    mma_f16(acc[i][j], af[i][0], af[i][1], af[i][2], af[i][3],
                            bf[j][0], bf[j][1]);
        }
        if (kt + 1 < KT) stsQ(buf ^ 1, kt + 1);
        asm volatile("cp.async.wait_group 0;" ::: "memory");
        __syncthreads();
    }

#pragma unroll
    for (int i = 0; i < 4; i++) {
        float v = qkp[i];
        v += __shfl_xor_sync(0xffffffffu, v, 1);
        v += __shfl_xor_sync(0xffffffffu, v, 2);
        if ((lane & 3) == 0) qks[qrow0 + 32 * i] = v;
    }
    __syncthreads();

#pragma unroll
    for (int i = 0; i < 4; i++) {
        const int row0 = wm + 16 * i + r;
        const float z0 = 1.0f / (qks[row0] + EPS_ATTN);
        const float z1 = 1.0f / (qks[row0 + 8] + EPS_ATTN);
        __half* op0 = Og + ((size_t)(n * LQ + l0 + row0)) * CH + h * HD;
        __half* op1 = Og + ((size_t)(n * LQ + l0 + row0 + 8)) * CH + h * HD;
#pragma unroll
        for (int j = 0; j < 8; j++) {
            const int col = wn + 8 * j + 2 * cq;
            __half2 h0 = __floats2half2_rn(acc[i][j][0] * z0, acc[i][j][1] * z0);
            __half2 h1 = __floats2half2_rn(acc[i][j][2] * z1, acc[i][j][3] * z1);
            *(__half2*)(op0 + col) = h0;
            *(__half2*)(op1 + col) = h1;
        }
    }
}

// ---------------- fused residual + LayerNorm (fp32 out + optional fp16 copy) ----------------
__global__ __launch_bounds__(256) void ln_res_kernel(
    const float* __restrict__ res, const float* __restrict__ y,
    const float* __restrict__ g, const float* __restrict__ b,
    float* __restrict__ out, __half* __restrict__ out_h) {
    const int row = blockIdx.x;
    const int t = threadIdx.x;
    const size_t off = (size_t)row * CH + t * 4;
    float4 v = *(const float4*)(y + off);
    __shared__ float red[8];
    const int lane = t & 31, w = t >> 5;

    float s = v.x + v.y + v.z + v.w;
#pragma unroll
    for (int o = 16; o; o >>= 1) s += __shfl_xor_sync(0xffffffffu, s, o);
    if (!lane) red[w] = s;
    __syncthreads();
    float tot = red[0];
#pragma unroll
    for (int i = 1; i < 8; i++) tot += red[i];
    const float mean = tot * (1.0f / CH);

    float dx = v.x - mean, dy = v.y - mean, dz = v.z - mean, dw = v.w - mean;
    float sq = dx * dx + dy * dy + dz * dz + dw * dw;
    __syncthreads();
#pragma unroll
    for (int o = 16; o; o >>= 1) sq += __shfl_xor_sync(0xffffffffu, sq, o);
    if (!lane) red[w] = sq;
    __syncthreads();
    float vtot = red[0];
#pragma unroll
    for (int i = 1; i < 8; i++) vtot += red[i];
    const float rstd = rsqrtf(vtot * (1.0f / CH) + EPS_LN);

    float4 gv = *(const float4*)(g + t * 4);
    float4 bv = *(const float4*)(b + t * 4);
    float4 rv = *(const float4*)(res + off);
    float4 o;
    o.x = rv.x + dx * rstd * gv.x + bv.x;
    o.y = rv.y + dy * rstd * gv.y + bv.y;
    o.z = rv.z + dz * rstd * gv.z + bv.z;
    o.w = rv.w + dw * rstd * gv.w + bv.w;
    *(float4*)(out + off) = o;
    if (out_h) {
        __half2 h0 = __floats2half2_rn(o.x, o.y);
        __half2 h1 = __floats2half2_rn(o.z, o.w);
        uint2 u;
        u.x = *(uint32_t*)&h0; u.y = *(uint32_t*)&h1;
        *(uint2*)(out_h + off) = u;
    }
}

// ---------------- host orchestration ----------------
extern "C" void kernel_launch(void* const* d_in, const int* in_sizes, int n_in,
                              void* d_out, int out_size) {
    const float* depth   = (const float*)d_in[0];
    const float* context = (const float*)d_in[1];
    const float* pos     = (const float*)d_in[2];
    const float* e_wq = (const float*)d_in[3];
    const float* e_wk = (const float*)d_in[4];
    const float* e_wv = (const float*)d_in[5];
    const float* e_wm = (const float*)d_in[6];
    const float* e_w1 = (const float*)d_in[7];
    const float* e_w2 = (const float*)d_in[8];
    const float* e_g1 = (const float*)d_in[9];
    const float* e_b1 = (const float*)d_in[10];
    const float* e_g2 = (const float*)d_in[11];
    const float* e_b2 = (const float*)d_in[12];
    const float* d_wq0 = (const float*)d_in[13];
    const float* d_wk0 = (const float*)d_in[14];
    const float* d_wv0 = (const float*)d_in[15];
    const float* d_wm0 = (const float*)d_in[16];
    const float* d_wq1 = (const float*)d_in[17];
    const float* d_wk1 = (const float*)d_in[18];
    const float* d_wv1 = (const float*)d_in[19];
    const float* d_wm1 = (const float*)d_in[20];
    const float* d_w1 = (const float*)d_in[21];
    const float* d_w2 = (const float*)d_in[22];
    const float* d_g0 = (const float*)d_in[23];
    const float* d_b0 = (const float*)d_in[24];
    const float* d_g1 = (const float*)d_in[25];
    const float* d_b1 = (const float*)d_in[26];
    const float* d_g2 = (const float*)d_in[27];
    const float* d_b2 = (const float*)d_in[28];
    float* out = (float*)d_out;

    float *ctx, *msg, *x, *yb, *kvp, *ksp, *ks;
    __half *ctxh, *xh, *ybh, *attnh, *deph, *hh, *qkvh;
    uint32_t *wt, *kvh;
    cudaGetSymbolAddress((void**)&ctx,   g_ctx);
    cudaGetSymbolAddress((void**)&msg,   g_msg);
    cudaGetSymbolAddress((void**)&x,     g_x);
    cudaGetSymbolAddress((void**)&yb,    g_y);
    cudaGetSymbolAddress((void**)&ctxh,  g_ctxh);
    cudaGetSymbolAddress((void**)&xh,    g_xh);
    cudaGetSymbolAddress((void**)&ybh,   g_yh);
    cudaGetSymbolAddress((void**)&attnh, g_attnh);
    cudaGetSymbolAddress((void**)&deph,  g_deph);
    cudaGetSymbolAddress((void**)&hh,    g_hh);
    cudaGetSymbolAddress((void**)&qkvh,  g_qkvh);
    cudaGetSymbolAddress((void**)&wt,    g_wt);
    cudaGetSymbolAddress((void**)&kvp,   g_kvpart);
    cudaGetSymbolAddress((void**)&kvh,   g_kvh);
    cudaGetSymbolAddress((void**)&ksp,   g_kspart);
    cudaGetSymbolAddress((void**)&ks,    g_ksum);

    cudaFuncSetAttribute(gemm_h<false, 0>, cudaFuncAttributeMaxDynamicSharedMemorySize, GEMM_SMEM2);
    cudaFuncSetAttribute(gemm_h<false, 2>, cudaFuncAttributeMaxDynamicSharedMemorySize, GEMM_SMEM2);
    cudaFuncSetAttribute(gemm_h<true, 2>,  cudaFuncAttributeMaxDynamicSharedMemorySize, GEMM_SMEM2);

    const size_t HM = 512 * 1024;
    uint32_t* w_qkvE = wt + 0 * HM;
    uint32_t* w_qkvD = wt + 3 * HM;
    uint32_t* w_kvD1 = wt + 6 * HM;
    uint32_t* w_q1   = wt + 8 * HM;
    uint32_t* w_em   = wt + 9 * HM;
    uint32_t* w_dm0  = wt + 10 * HM;
    uint32_t* w_dm1  = wt + 11 * HM;
    uint32_t* w_e1   = wt + 12 * HM;
    uint32_t* w_d1   = wt + 14 * HM;
    uint32_t* w_e2   = wt + 16 * HM;
    uint32_t* w_d2   = wt + 18 * HM;

    PKArgs pk;
    auto seg = [&](int i, const float* s, uint32_t* d, int K, int lgN, int ostr, int co) {
        pk.src[i] = s; pk.dst[i] = d;
        pk.total[i] = (K / 2) << lgN;
        pk.lgN[i] = lgN; pk.ostride[i] = ostr; pk.colofs[i] = co;
    };
    seg(0,  e_wq,  w_qkvE, 1024, 10, 3072, 0);
    seg(1,  e_wk,  w_qkvE, 1024, 10, 3072, 1024);
    seg(2,  e_wv,  w_qkvE, 1024, 10, 3072, 2048);
    seg(3,  d_wq0, w_qkvD, 1024, 10, 3072, 0);
    seg(4,  d_wk0, w_qkvD, 1024, 10, 3072, 1024);
    seg(5,  d_wv0, w_qkvD, 1024, 10, 3072, 2048);
    seg(6,  d_wk1, w_kvD1, 1024, 10, 2048, 0);
    seg(7,  d_wv1, w_kvD1, 1024, 10, 2048, 1024);
    seg(8,  d_wq1, w_q1,  1024, 10, 1024, 0);
    seg(9,  e_wm,  w_em,  1024, 10, 1024, 0);
    seg(10, d_wm0, w_dm0, 1024, 10, 1024, 0);
    seg(11, d_wm1, w_dm1, 1024, 10, 1024, 0);
    seg(12, e_w1, w_e1, 1024, 11, 2048, 0);
    seg(13, d_w1, w_d1, 1024, 11, 2048, 0);
    seg(14, e_w2, w_e2, 2048, 10, 1024, 0);
    seg(15, d_w2, w_d2, 2048, 10, 1024, 0);
    seg(16, depth, (uint32_t*)deph, NL * CH, 0, 1, 0);
    pack_w<<<dim3(256, 17), 256>>>(pk);

    const dim3 blk(256);
    const dim3 gblk(128);
    const dim3 gemmblk(256);
    const dim3 gU(CH / 128, NL / 256);          // (8, 32)
    const dim3 gF(2 * CH / 128, NL / 256);      // (16, 32)
    const dim3 gQKV(3 * CH / 128, NL / 256);    // (24, 32)

    auto attention = [&](const __half* qp, int ldq, const __half* kp, const __half* vp, int ldkv) {
        attn_kv_h<<<dim3(NHT, KVSPLIT), gblk>>>(kp, vp, ldkv, kvp, ksp);
        kv_reduce_h<<<(NHT * (HD / 2) * HD + 255) / 256, blk>>>(kvp, kvh);
        ks_reduce_kernel<<<NHT, 128>>>(ksp, ks);
        attn_out_h<<<dim3(LQ / 128, NHT), gblk>>>(qp, ldq, kvh, ks, attnh);
    };

    // ===== encoder =====
    add_kernel<<<2048, blk>>>(context, pos, ctx, ctxh, NL * CH / 4);
    gemm_h<false, 2><<<gQKV, gemmblk, GEMM_SMEM2>>>((const uint32_t*)ctxh, w_qkvE, qkvh, NL, 512, 3 * CH);
    attention(qkvh, 3 * CH, qkvh + CH, qkvh + 2 * CH, 3 * CH);
    gemm_h<false, 0><<<gU, gemmblk, GEMM_SMEM2>>>((const uint32_t*)attnh, w_em, msg, NL, 512, CH);
    ln_res_kernel<<<NL, blk>>>(ctx, msg, e_g1, e_b1, x, xh);
    gemm_h<true, 2><<<gF, gemmblk, GEMM_SMEM2>>>((const uint32_t*)xh, w_e1, hh, NL, 512, 2 * CH);
    gemm_h<false, 0><<<gU, gemmblk, GEMM_SMEM2>>>((const uint32_t*)hh, w_e2, msg, NL, 1024, CH);
    ln_res_kernel<<<NL, blk>>>(x, msg, e_g2, e_b2, ctx, ctxh);

    // ===== decoder: self-attention =====
    gemm_h<false, 2><<<gQKV, gemmblk, GEMM_SMEM2>>>((const uint32_t*)deph, w_qkvD, qkvh, NL, 512, 3 * CH);
    attention(qkvh, 3 * CH, qkvh + CH, qkvh + 2 * CH, 3 * CH);
    gemm_h<false, 0><<<gU, gemmblk, GEMM_SMEM2>>>((const uint32_t*)attnh, w_dm0, msg, NL, 512, CH);
    ln_res_kernel<<<NL, blk>>>(depth, msg, d_g0, d_b0, x, xh);

    // ===== decoder: cross-attention =====
    {
        __half* crossq = qkvh;
        __half* crosskv = qkvh + (size_t)NL * CH;
        gemm_h<false, 2><<<gU, gemmblk, GEMM_SMEM2>>>((const uint32_t*)xh, w_q1, crossq, NL, 512, CH);
        gemm_h<false, 2><<<gF, gemmblk, GEMM_SMEM2>>>((const uint32_t*)ctxh, w_kvD1, crosskv, NL, 512, 2 * CH);
        attention(crossq, CH, crosskv, crosskv + CH, 2 * CH);
    }
    gemm_h<false, 0><<<gU, gemmblk, GEMM_SMEM2>>>((const uint32_t*)attnh, w_dm1, msg, NL, 512, CH);
    ln_res_kernel<<<NL, blk>>>(x, msg, d_g1, d_b1, yb, ybh);

    // ===== decoder: FFN =====
    gemm_h<true, 2><<<gF, gemmblk, GEMM_SMEM2>>>((const uint32_t*)ybh, w_d1, hh, NL, 512, 2 * CH);
    gemm_h<false, 0><<<gU, gemmblk, GEMM_SMEM2>>>((const uint32_t*)hh, w_d2, msg, NL, 1024, CH);
    ln_res_kernel<<<NL, blk>>>(yb, msg, d_g2, d_b2, out, nullptr);
}

// round 17
// speedup vs baseline: 1.1479x; 1.1479x over previous
#include <cuda_runtime.h>
#include <cuda_fp16.h>
#include <cstdint>
#include <math.h>

#define NB 4
#define LQ 2048
#define CH 1024
#define NHD 8
#define HD 128
#define NL (NB * LQ)
#define NHT (NB * NHD)
#define KVSPLIT 16
#define EPS_ATTN 1e-6f
#define EPS_LN 1e-5f

// fp16 GEMM tiles: CTA 128x128, 32 words (64 halves) K per stage, 2 stages, 3 CTAs/SM
#define BSTR 136
#define ASTR2 36
#define A2_WORDS (128 * ASTR2)            // 4608
#define B2_WORDS (32 * BSTR)              // 4352
#define STG2_WORDS (A2_WORDS + B2_WORDS)  // 8960
#define GEMM_SMEM2 (2 * STG2_WORDS * 4)   // 71680

// fp16 attention tiles
#define KH_ASTR 17     // Kt/Qs stride (words)
#define VSTR 137       // attn_kv V stride (scalar STS only)
#define BCP_STR 136    // attn_out B stride (cp.async 16B-aligned rows)

// ---------------- scratch (256B-aligned) ----------------
__device__ __align__(256) float g_ctx[NL * CH];
__device__ __align__(256) float g_msg[NL * CH];
__device__ __align__(256) float g_x[NL * CH];
__device__ __align__(256) float g_y[NL * CH];
__device__ __align__(256) __half g_ctxh[NL * CH];
__device__ __align__(256) __half g_xh[NL * CH];
__device__ __align__(256) __half g_yh[NL * CH];
__device__ __align__(256) __half g_attnh[NL * CH];
__device__ __align__(256) __half g_deph[NL * CH];
__device__ __align__(256) __half g_hh[NL * 2 * CH];
__device__ __align__(256) __half g_qkvh[NL * 3 * CH];
__device__ __align__(256) uint32_t g_wt[12 * 1024 * 1024];
__device__ __align__(256) float g_kvpart[KVSPLIT * NHT * HD * HD];
__device__ __align__(256) uint32_t g_kvh[NHT * (HD / 2) * HD];
__device__ __align__(256) float g_kspart[KVSPLIT * NHT * HD];
__device__ __align__(256) float g_ksum[NHT * HD];

__device__ __forceinline__ float fmap(float x) { return x > 0.0f ? x + 1.0f : expf(x); }

__device__ __forceinline__ void cp16(uint32_t saddr, const void* g) {
    asm volatile("cp.async.cg.shared.global [%0], [%1], 16;" :: "r"(saddr), "l"(g));
}

__device__ __forceinline__ uint32_t smem_u32(const void* p) {
    uint32_t a;
    asm("{ .reg .u64 t; cvta.to.shared.u64 t, %1; cvt.u32.u64 %0, t; }" : "=r"(a) : "l"(p));
    return a;
}

__device__ __forceinline__ void mma_f16(float* d,
                                        uint32_t a0, uint32_t a1, uint32_t a2, uint32_t a3,
                                        uint32_t b0, uint32_t b1) {
    asm volatile(
        "mma.sync.aligned.m16n8k16.row.col.f32.f16.f16.f32 "
        "{%0,%1,%2,%3}, {%4,%5,%6,%7}, {%8,%9}, {%0,%1,%2,%3};"
        : "+f"(d[0]), "+f"(d[1]), "+f"(d[2]), "+f"(d[3])
        : "r"(a0), "r"(a1), "r"(a2), "r"(a3), "r"(b0), "r"(b1));
}

// ---------------- weight pack: fp32 [K][N] -> half2 words [K/2][ostride] ----------------
struct PKArgs {
    const float* src[17];
    uint32_t* dst[17];
    int total[17];
    int lgN[17];
    int ostride[17];
    int colofs[17];
};
__global__ void pack_w(PKArgs a) {
    const int seg = blockIdx.y;
    const float* __restrict__ s = a.src[seg];
    uint32_t* __restrict__ d = a.dst[seg];
    const int total = a.total[seg];
    const int lg = a.lgN[seg];
    const int Nm = (1 << lg) - 1;
    const int ostr = a.ostride[seg];
    const int co = a.colofs[seg];
    int idx = blockIdx.x * blockDim.x + threadIdx.x;
    int stride = gridDim.x * blockDim.x;
    for (int i = idx; i < total; i += stride) {
        int n = i & Nm;
        int k2 = i >> lg;
        size_t slo = ((size_t)k2 << (lg + 1)) + n;
        float lo = s[slo];
        float hi = s[slo + (1 << lg)];
        __half2 h = __floats2half2_rn(lo, hi);
        d[(size_t)k2 * ostr + co + n] = *(uint32_t*)&h;
    }
}

// ---------------- fp16 GEMM: CTA 128x128, 128 thr, 4 warps (2x2 of 64x64), 3 CTAs/SM ------
// OUTM: 0 = fp32 out, 2 = fp16 out
template <bool RELU, int OUTM>
__global__ __launch_bounds__(128, 3) void gemm_h(
    const uint32_t* __restrict__ Aw, const uint32_t* __restrict__ Bw, void* __restrict__ Cout,
    int M, int Kw, int Nn) {
    extern __shared__ uint32_t sm[];
    const uint32_t smaddr = smem_u32(sm);
    const int tid = threadIdx.x;
    const int wid = tid >> 5, lane = tid & 31;
    const int bm = blockIdx.y * 128;
    const int bn = blockIdx.x * 128;
    const int wm = (wid & 1) * 64;
    const int wn = (wid >> 1) * 64;
    const int r = lane >> 2, cq = lane & 3;

    float acc[4][8][4];
#pragma unroll
    for (int i = 0; i < 4; i++)
#pragma unroll
        for (int j = 0; j < 8; j++)
#pragma unroll
            for (int c = 0; c < 4; c++) acc[i][j][c] = 0.0f;

    const int KT = Kw / 32;

    auto issue = [&](int s, int kt) {
        const uint32_t sbA = smaddr + s * (STG2_WORDS * 4);
        const uint32_t* Ag = Aw + (size_t)bm * Kw + (size_t)kt * 32;
#pragma unroll
        for (int i = 0; i < 8; i++) {
            int idx = tid + 128 * i;
            int row = idx >> 3, c4 = (idx & 7) * 4;
            cp16(sbA + (row * ASTR2 + c4) * 4, Ag + (size_t)row * Kw + c4);
        }
        const uint32_t sbB = sbA + A2_WORDS * 4;
        const uint32_t* Bg = Bw + (size_t)(kt * 32) * Nn + bn;
#pragma unroll
        for (int i = 0; i < 8; i++) {
            int idx = tid + 128 * i;
            int kk = idx >> 5, n4 = (idx & 31) * 4;
            cp16(sbB + (kk * BSTR + n4) * 4, Bg + (size_t)kk * Nn + n4);
        }
        asm volatile("cp.async.commit_group;" ::: "memory");
    };

    issue(0, 0);

    for (int kt = 0; kt < KT; kt++) {
        const int buf = kt & 1;
        asm volatile("cp.async.wait_group 0;" ::: "memory");
        __syncthreads();
        if (kt + 1 < KT) issue(buf ^ 1, kt + 1);

        const uint32_t* Asb = sm + buf * STG2_WORDS;
        const uint32_t* Bsb = Asb + A2_WORDS;
#pragma unroll
        for (int s = 0; s < 4; s++) {
            uint32_t af[4][4];
#pragma unroll
            for (int i = 0; i < 4; i++) {
                const int arow = wm + 16 * i + r;
                const int kc = 8 * s + cq;
                af[i][0] = Asb[arow * ASTR2 + kc];
                af[i][1] = Asb[(arow + 8) * ASTR2 + kc];
                af[i][2] = Asb[arow * ASTR2 + kc + 4];
                af[i][3] = Asb[(arow + 8) * ASTR2 + kc + 4];
            }
            uint32_t bf[8][2];
#pragma unroll
            for (int j = 0; j < 8; j++) {
                const int ncol = wn + 8 * j + r;
                bf[j][0] = Bsb[(8 * s + cq) * BSTR + ncol];
                bf[j][1] = Bsb[(8 * s + cq + 4) * BSTR + ncol];
            }
#pragma unroll
            for (int i = 0; i < 4; i++)
#pragma unroll
                for (int j = 0; j < 8; j++)
                    mma_f16(acc[i][j], af[i][0], af[i][1], af[i][2], af[i][3],
                            bf[j][0], bf[j][1]);
        }
    }

#pragma unroll
    for (int i = 0; i < 4; i++) {
        const int row0 = bm + wm + 16 * i + r;
#pragma unroll
        for (int j = 0; j < 8; j++) {
            const int col = bn + wn + 8 * j + 2 * cq;
            float v[4] = {acc[i][j][0], acc[i][j][1], acc[i][j][2], acc[i][j][3]};
            if (RELU) {
#pragma unroll
                for (int c = 0; c < 4; c++) v[c] = fmaxf(v[c], 0.f);
            }
            if (OUTM == 2) {
                __half* Ch = (__half*)Cout;
                __half2 h0 = __floats2half2_rn(v[0], v[1]);
                __half2 h1 = __floats2half2_rn(v[2], v[3]);
                *(__half2*)(Ch + (size_t)row0 * Nn + col) = h0;
                *(__half2*)(Ch + (size_t)(row0 + 8) * Nn + col) = h1;
            } else {
                float* Cf = (float*)Cout;
                float2 v0, v1;
                v0.x = v[0]; v0.y = v[1]; v1.x = v[2]; v1.y = v[3];
                *(float2*)(Cf + (size_t)row0 * Nn + col) = v0;
                *(float2*)(Cf + (size_t)(row0 + 8) * Nn + col) = v1;
            }
        }
    }
}

// ---------------- elementwise add (fp32 out + fp16 copy) ----------------
__global__ void add_kernel(const float* __restrict__ a, const float* __restrict__ b,
                           float* __restrict__ o, __half* __restrict__ oh, int n4) {
    int idx = blockIdx.x * blockDim.x + threadIdx.x;
    int stride = gridDim.x * blockDim.x;
    const float4* a4 = (const float4*)a;
    const float4* b4 = (const float4*)b;
    float4* o4 = (float4*)o;
    for (int i = idx; i < n4; i += stride) {
        float4 x = a4[i], y = b4[i];
        x.x += y.x; x.y += y.y; x.z += y.z; x.w += y.w;
        o4[i] = x;
        __half2 h0 = __floats2half2_rn(x.x, x.y);
        __half2 h1 = __floats2half2_rn(x.z, x.w);
        uint2 u;
        u.x = *(uint32_t*)&h0; u.y = *(uint32_t*)&h1;
        *(uint2*)(oh + (size_t)i * 4) = u;
    }
}

// ---------------- fp16 attn KV: KV = fmap(K)^T @ V over L-slice + ksum ----------------
__global__ __launch_bounds__(128) void attn_kv_h(
    const __half* __restrict__ Kg, const __half* __restrict__ Vg, int ld,
    float* __restrict__ kvpart, float* __restrict__ kspart) {
    __shared__ uint32_t Kt[2][128 * KH_ASTR];  // [d][w]
    __shared__ uint32_t Vs[2][16 * VSTR];      // [w][v]
    __shared__ float ksp[16][129];

    const int nh = blockIdx.x;
    const int split = blockIdx.y;
    const int n = nh >> 3, h = nh & 7;
    const int lbase = split * (LQ / KVSPLIT);
    const int tid = threadIdx.x;
    const int wid = tid >> 5, lane = tid & 31;
    const int wm = (wid & 1) * 64;
    const int wn = (wid >> 1) * 64;
    const int r = lane >> 2, cq = lane & 3;

    const int w = tid & 15;
    const int db = (tid >> 4) * 16;
    const size_t base = ((size_t)(n * LQ + lbase)) * ld + h * HD;

    float acc[4][8][4];
#pragma unroll
    for (int i = 0; i < 4; i++)
#pragma unroll
        for (int j = 0; j < 8; j++)
#pragma unroll
            for (int c = 0; c < 4; c++) acc[i][j][c] = 0.0f;
    float kacc[16];
#pragma unroll
    for (int i = 0; i < 16; i++) kacc[i] = 0.0f;

    uint4 kr[4], vr[4];
    const int KT = (LQ / KVSPLIT) / 32;   // 4

    auto ldg = [&](int kt) {
        const __half* kp = Kg + base + (size_t)(kt * 32 + 2 * w) * ld + db;
        kr[0] = *(const uint4*)kp;
        kr[1] = *(const uint4*)(kp + 8);
        kr[2] = *(const uint4*)(kp + ld);
        kr[3] = *(const uint4*)(kp + ld + 8);
        const __half* vp = Vg + base + (size_t)(kt * 32 + 2 * w) * ld + db;
        vr[0] = *(const uint4*)vp;
        vr[1] = *(const uint4*)(vp + 8);
        vr[2] = *(const uint4*)(vp + ld);
        vr[3] = *(const uint4*)(vp + ld + 8);
    };
    auto sts = [&](int buf) {
        const __half* kh = (const __half*)kr;
        const __half* vh = (const __half*)vr;
#pragma unroll
        for (int i = 0; i < 16; i++) {
            float lo = fmap(__half2float(kh[i]));
            float hi = fmap(__half2float(kh[16 + i]));
            __half2 p = __floats2half2_rn(lo, hi);
            float2 pr = __half22float2(p);
            kacc[i] += pr.x + pr.y;
            Kt[buf][(db + i) * KH_ASTR + w] = *(uint32_t*)&p;
            __half2 pv = __halves2half2(vh[i], vh[16 + i]);
            Vs[buf][w * VSTR + db + i] = *(uint32_t*)&pv;
        }
    };

    ldg(0);
    sts(0);
    __syncthreads();

    for (int kt = 0; kt < KT; kt++) {
        const int buf = kt & 1;
        if (kt + 1 < KT) ldg(kt + 1);

        const uint32_t* Asb = Kt[buf];
        const uint32_t* Bsb = Vs[buf];
#pragma unroll
        for (int s = 0; s < 2; s++) {
            uint32_t af[4][4];
#pragma unroll
            for (int i = 0; i < 4; i++) {
                const int arow = wm + 16 * i + r;
                const int kc = 8 * s + cq;
                af[i][0] = Asb[arow * KH_ASTR + kc];
                af[i][1] = Asb[(arow + 8) * KH_ASTR + kc];
                af[i][2] = Asb[arow * KH_ASTR + kc + 4];
                af[i][3] = Asb[(arow + 8) * KH_ASTR + kc + 4];
            }
            uint32_t bf[8][2];
#pragma unroll
            for (int j = 0; j < 8; j++) {
                const int ncol = wn + 8 * j + r;
                bf[j][0] = Bsb[(8 * s + cq) * VSTR + ncol];
                bf[j][1] = Bsb[(8 * s + cq + 4) * VSTR + ncol];
            }
#pragma unroll
            for (int i = 0; i < 4; i++)
#pragma unroll
                for (int j = 0; j < 8; j++)
                    mma_f16(acc[i][j], af[i][0], af[i][1], af[i][2], af[i][3],
                            bf[j][0], bf[j][1]);
        }
        if (kt + 1 < KT) sts(buf ^ 1);
        __syncthreads();
    }

    float* o = kvpart + (((size_t)(split * NHT + nh)) << 14);
#pragma unroll
    for (int i = 0; i < 4; i++) {
        const int row0 = wm + 16 * i + r;
#pragma unroll
        for (int j = 0; j < 8; j++) {
            const int col = wn + 8 * j + 2 * cq;
            float2 v0, v1;
            v0.x = acc[i][j][0]; v0.y = acc[i][j][1];
            v1.x = acc[i][j][2]; v1.y = acc[i][j][3];
            *(float2*)(o + (size_t)row0 * HD + col) = v0;
            *(float2*)(o + (size_t)(row0 + 8) * HD + col) = v1;
        }
    }

#pragma unroll
    for (int i = 0; i < 16; i++) ksp[w][db + i] = kacc[i];
    __syncthreads();
    {
        int d = tid;
        float s = 0.0f;
#pragma unroll
        for (int j = 0; j < 16; j++) s += ksp[j][d];
        kspart[(split * NHT + nh) * HD + d] = s;
    }
}

// ---------------- KV reduce -> packed half2 words [d/2][v] ----------------
__global__ void kv_reduce_h(const float* __restrict__ part, uint32_t* __restrict__ kvh) {
    int idx = blockIdx.x * 256 + threadIdx.x;
    if (idx < NHT * (HD / 2) * HD) {
        int nh = idx >> 13;
        int d2 = (idx >> 7) & 63;
        int v = idx & 127;
        float lo = 0.0f, hi = 0.0f;
#pragma unroll
        for (int sp = 0; sp < KVSPLIT; sp++) {
            const float* p = part + (((size_t)(sp * NHT + nh)) << 14);
            lo += p[(2 * d2) * HD + v];
            hi += p[(2 * d2 + 1) * HD + v];
        }
        __half2 h = __floats2half2_rn(lo, hi);
        kvh[idx] = *(uint32_t*)&h;
    }
}

__global__ void ks_reduce_kernel(const float* __restrict__ part, float* __restrict__ ks) {
    int idx = blockIdx.x * 128 + threadIdx.x;
    int nh = idx >> 7, d = idx & 127;
    float s = 0.0f;
#pragma unroll
    for (int sp = 0; sp < KVSPLIT; sp++)
        s += part[(sp * NHT + nh) * HD + d];
    ks[idx] = s;
}

// ---------------- fp16 attn out: O = fmap(Q) @ KV * Z ----------------
__global__ __launch_bounds__(128) void attn_out_h(
    const __half* __restrict__ Qg, int ldq, const uint32_t* __restrict__ KVh,
    const float* __restrict__ Ksum, __half* __restrict__ Og) {
    __shared__ uint32_t Qs[2][128 * KH_ASTR];
    __shared__ uint32_t Bs[2][16 * BCP_STR];
    __shared__ float kss[HD];
    __shared__ float qks[128];
    const uint32_t BsAddr = smem_u32(Bs);

    const int nh = blockIdx.y;
    const int n = nh >> 3, h = nh & 7;
    const int l0 = blockIdx.x * 128;
    const int tid = threadIdx.x;
    const int wid = tid >> 5, lane = tid & 31;
    const int wm = (wid & 1) * 64;
    const int wn = (wid >> 1) * 64;
    const int r = lane >> 2, cq = lane & 3;

    kss[tid] = Ksum[nh * HD + tid];

    const size_t qbase = ((size_t)(n * LQ + l0)) * ldq + h * HD;
    const uint32_t* kvb = KVh + ((size_t)nh << 13);

    const int qrow0 = tid >> 2;
    const int qw4 = (tid & 3) * 4;

    float acc[4][8][4];
#pragma unroll
    for (int i = 0; i < 4; i++)
#pragma unroll
        for (int j = 0; j < 8; j++)
#pragma unroll
            for (int c = 0; c < 4; c++) acc[i][j][c] = 0.0f;
    float qkp[4] = {0.f, 0.f, 0.f, 0.f};

    uint4 qr[4];
    const int KT = HD / 32;   // 4

    auto ldgQ = [&](int kt) {
#pragma unroll
        for (int i = 0; i < 4; i++)
            qr[i] = *(const uint4*)(Qg + qbase + (size_t)(qrow0 + 32 * i) * ldq + kt * 32 + qw4 * 2);
    };
    auto stsQ = [&](int buf, int kt) {
#pragma unroll
        for (int i = 0; i < 4; i++) {
            const __half* qh = (const __half*)&qr[i];
#pragma unroll
            for (int j = 0; j < 4; j++) {
                float lo = fmap(__half2float(qh[2 * j]));
                float hi = fmap(__half2float(qh[2 * j + 1]));
                __half2 p = __floats2half2_rn(lo, hi);
                float2 pr = __half22float2(p);
                const int dc = kt * 32 + (qw4 + j) * 2;
                qkp[i] += pr.x * kss[dc] + pr.y * kss[dc + 1];
                Qs[buf][(qrow0 + 32 * i) * KH_ASTR + qw4 + j] = *(uint32_t*)&p;
            }
        }
    };
    auto cpB = [&](int buf, int kt) {
#pragma unroll
        for (int i = 0; i < 4; i++) {
            int idx = tid + 128 * i;
            int kk = idx >> 5, v4 = (idx & 31) * 4;
            cp16(BsAddr + (buf * (16 * BCP_STR) + kk * BCP_STR + v4) * 4,
                 kvb + (size_t)(kt * 16 + kk) * HD + v4);
        }
        asm volatile("cp.async.commit_group;" ::: "memory");
    };

    ldgQ(0);
    cpB(0, 0);
    __syncthreads();   // kss visible to all warps BEFORE first stsQ reads it
    stsQ(0, 0);
    asm volatile("cp.async.wait_group 0;" ::: "memory");
    __syncthreads();

    for (int kt = 0; kt < KT; kt++) {
        const int buf = kt & 1;
        if (kt + 1 < KT) {
            cpB(buf ^ 1, kt + 1);
            ldgQ(kt + 1);
        }
        const uint32_t* Asb = Qs[buf];
        const uint32_t* Bsb = Bs[buf];
#pragma unroll
        for (int s = 0; s < 2; s++) {
            uint32_t af[4][4];
#pragma unroll
            for (int i = 0; i < 4; i++) {
                const int arow = wm + 16 * i + r;
                const int kc = 8 * s + cq;
                af[i][0] = Asb[arow * KH_ASTR + kc];
                af[i][1] = Asb[(arow + 8) * KH_ASTR + kc];
                af[i][2] = Asb[arow * KH_ASTR + kc + 4];
                af[i][3] = Asb[(arow + 8) * KH_ASTR + kc + 4];
            }
            uint32_t bf[8][2];
#pragma unroll
            for (int j = 0; j < 8; j++) {
                const int ncol = wn + 8 * j + r;
                bf[j][0] = Bsb[(8 * s + cq) * BCP_STR + ncol];
                bf[j][1] = Bsb[(8 * s + cq + 4) * BCP_STR + ncol];
            }
#pragma unroll
            for (int i = 0; i < 4; i++)
#pragma unroll
                for (int j = 0; j < 8; j++)
                    mma_f16(acc[i][j], af[i][0], af[i][1], af[i][2], af[i][3],
                            bf[j][0], bf[j][1]);
        }
        if (kt + 1 < KT) stsQ(buf ^ 1, kt + 1);
        asm volatile("cp.async.wait_group 0;" ::: "memory");
        __syncthreads();
    }

#pragma unroll
    for (int i = 0; i < 4; i++) {
        float v = qkp[i];
        v += __shfl_xor_sync(0xffffffffu, v, 1);
        v += __shfl_xor_sync(0xffffffffu, v, 2);
        if ((lane & 3) == 0) qks[qrow0 + 32 * i] = v;
    }
    __syncthreads();

#pragma unroll
    for (int i = 0; i < 4; i++) {
        const int row0 = wm + 16 * i + r;
        const float z0 = 1.0f / (qks[row0] + EPS_ATTN);
        const float z1 = 1.0f / (qks[row0 + 8] + EPS_ATTN);
        __half* op0 = Og + ((size_t)(n * LQ + l0 + row0)) * CH + h * HD;
        __half* op1 = Og + ((size_t)(n * LQ + l0 + row0 + 8)) * CH + h * HD;
#pragma unroll
        for (int j = 0; j < 8; j++) {
            const int col = wn + 8 * j + 2 * cq;
            __half2 h0 = __floats2half2_rn(acc[i][j][0] * z0, acc[i][j][1] * z0);
            __half2 h1 = __floats2half2_rn(acc[i][j][2] * z1, acc[i][j][3] * z1);
            *(__half2*)(op0 + col) = h0;
            *(__half2*)(op1 + col) = h1;
        }
    }
}

// ---------------- fused residual + LayerNorm (fp32 out + optional fp16 copy) ----------------
__global__ __launch_bounds__(256) void ln_res_kernel(
    const float* __restrict__ res, const float* __restrict__ y,
    const float* __restrict__ g, const float* __restrict__ b,
    float* __restrict__ out, __half* __restrict__ out_h) {
    const int row = blockIdx.x;
    const int t = threadIdx.x;
    const size_t off = (size_t)row * CH + t * 4;
    float4 v = *(const float4*)(y + off);
    __shared__ float red[8];
    const int lane = t & 31, w = t >> 5;

    float s = v.x + v.y + v.z + v.w;
#pragma unroll
    for (int o = 16; o; o >>= 1) s += __shfl_xor_sync(0xffffffffu, s, o);
    if (!lane) red[w] = s;
    __syncthreads();
    float tot = red[0];
#pragma unroll
    for (int i = 1; i < 8; i++) tot += red[i];
    const float mean = tot * (1.0f / CH);

    float dx = v.x - mean, dy = v.y - mean, dz = v.z - mean, dw = v.w - mean;
    float sq = dx * dx + dy * dy + dz * dz + dw * dw;
    __syncthreads();
#pragma unroll
    for (int o = 16; o; o >>= 1) sq += __shfl_xor_sync(0xffffffffu, sq, o);
    if (!lane) red[w] = sq;
    __syncthreads();
    float vtot = red[0];
#pragma unroll
    for (int i = 1; i < 8; i++) vtot += red[i];
    const float rstd = rsqrtf(vtot * (1.0f / CH) + EPS_LN);

    float4 gv = *(const float4*)(g + t * 4);
    float4 bv = *(const float4*)(b + t * 4);
    float4 rv = *(const float4*)(res + off);
    float4 o;
    o.x = rv.x + dx * rstd * gv.x + bv.x;
    o.y = rv.y + dy * rstd * gv.y + bv.y;
    o.z = rv.z + dz * rstd * gv.z + bv.z;
    o.w = rv.w + dw * rstd * gv.w + bv.w;
    *(float4*)(out + off) = o;
    if (out_h) {
        __half2 h0 = __floats2half2_rn(o.x, o.y);
        __half2 h1 = __floats2half2_rn(o.z, o.w);
        uint2 u;
        u.x = *(uint32_t*)&h0; u.y = *(uint32_t*)&h1;
        *(uint2*)(out_h + off) = u;
    }
}

// ---------------- host orchestration ----------------
extern "C" void kernel_launch(void* const* d_in, const int* in_sizes, int n_in,
                              void* d_out, int out_size) {
    const float* depth   = (const float*)d_in[0];
    const float* context = (const float*)d_in[1];
    const float* pos     = (const float*)d_in[2];
    const float* e_wq = (const float*)d_in[3];
    const float* e_wk = (const float*)d_in[4];
    const float* e_wv = (const float*)d_in[5];
    const float* e_wm = (const float*)d_in[6];
    const float* e_w1 = (const float*)d_in[7];
    const float* e_w2 = (const float*)d_in[8];
    const float* e_g1 = (const float*)d_in[9];
    const float* e_b1 = (const float*)d_in[10];
    const float* e_g2 = (const float*)d_in[11];
    const float* e_b2 = (const float*)d_in[12];
    const float* d_wq0 = (const float*)d_in[13];
    const float* d_wk0 = (const float*)d_in[14];
    const float* d_wv0 = (const float*)d_in[15];
    const float* d_wm0 = (const float*)d_in[16];
    const float* d_wq1 = (const float*)d_in[17];
    const float* d_wk1 = (const float*)d_in[18];
    const float* d_wv1 = (const float*)d_in[19];
    const float* d_wm1 = (const float*)d_in[20];
    const float* d_w1 = (const float*)d_in[21];
    const float* d_w2 = (const float*)d_in[22];
    const float* d_g0 = (const float*)d_in[23];
    const float* d_b0 = (const float*)d_in[24];
    const float* d_g1 = (const float*)d_in[25];
    const float* d_b1 = (const float*)d_in[26];
    const float* d_g2 = (const float*)d_in[27];
    const float* d_b2 = (const float*)d_in[28];
    float* out = (float*)d_out;

    float *ctx, *msg, *x, *yb, *kvp, *ksp, *ks;
    __half *ctxh, *xh, *ybh, *attnh, *deph, *hh, *qkvh;
    uint32_t *wt, *kvh;
    cudaGetSymbolAddress((void**)&ctx,   g_ctx);
    cudaGetSymbolAddress((void**)&msg,   g_msg);
    cudaGetSymbolAddress((void**)&x,     g_x);
    cudaGetSymbolAddress((void**)&yb,    g_y);
    cudaGetSymbolAddress((void**)&ctxh,  g_ctxh);
    cudaGetSymbolAddress((void**)&xh,    g_xh);
    cudaGetSymbolAddress((void**)&ybh,   g_yh);
    cudaGetSymbolAddress((void**)&attnh, g_attnh);
    cudaGetSymbolAddress((void**)&deph,  g_deph);
    cudaGetSymbolAddress((void**)&hh,    g_hh);
    cudaGetSymbolAddress((void**)&qkvh,  g_qkvh);
    cudaGetSymbolAddress((void**)&wt,    g_wt);
    cudaGetSymbolAddress((void**)&kvp,   g_kvpart);
    cudaGetSymbolAddress((void**)&kvh,   g_kvh);
    cudaGetSymbolAddress((void**)&ksp,   g_kspart);
    cudaGetSymbolAddress((void**)&ks,    g_ksum);

    cudaFuncSetAttribute(gemm_h<false, 0>, cudaFuncAttributeMaxDynamicSharedMemorySize, GEMM_SMEM2);
    cudaFuncSetAttribute(gemm_h<false, 2>, cudaFuncAttributeMaxDynamicSharedMemorySize, GEMM_SMEM2);
    cudaFuncSetAttribute(gemm_h<true, 2>,  cudaFuncAttributeMaxDynamicSharedMemorySize, GEMM_SMEM2);

    const size_t HM = 512 * 1024;
    uint32_t* w_qkvE = wt + 0 * HM;
    uint32_t* w_qkvD = wt + 3 * HM;
    uint32_t* w_kvD1 = wt + 6 * HM;
    uint32_t* w_q1   = wt + 8 * HM;
    uint32_t* w_em   = wt + 9 * HM;
    uint32_t* w_dm0  = wt + 10 * HM;
    uint32_t* w_dm1  = wt + 11 * HM;
    uint32_t* w_e1   = wt + 12 * HM;
    uint32_t* w_d1   = wt + 14 * HM;
    uint32_t* w_e2   = wt + 16 * HM;
    uint32_t* w_d2   = wt + 18 * HM;

    PKArgs pk;
    auto seg = [&](int i, const float* s, uint32_t* d, int K, int lgN, int ostr, int co) {
        pk.src[i] = s; pk.dst[i] = d;
        pk.total[i] = (K / 2) << lgN;
        pk.lgN[i] = lgN; pk.ostride[i] = ostr; pk.colofs[i] = co;
    };
    seg(0,  e_wq,  w_qkvE, 1024, 10, 3072, 0);
    seg(1,  e_wk,  w_qkvE, 1024, 10, 3072, 1024);
    seg(2,  e_wv,  w_qkvE, 1024, 10, 3072, 2048);
    seg(3,  d_wq0, w_qkvD, 1024, 10, 3072, 0);
    seg(4,  d_wk0, w_qkvD, 1024, 10, 3072, 1024);
    seg(5,  d_wv0, w_qkvD, 1024, 10, 3072, 2048);
    seg(6,  d_wk1, w_kvD1, 1024, 10, 2048, 0);
    seg(7,  d_wv1, w_kvD1, 1024, 10, 2048, 1024);
    seg(8,  d_wq1, w_q1,  1024, 10, 1024, 0);
    seg(9,  e_wm,  w_em,  1024, 10, 1024, 0);
    seg(10, d_wm0, w_dm0, 1024, 10, 1024, 0);
    seg(11, d_wm1, w_dm1, 1024, 10, 1024, 0);
    seg(12, e_w1, w_e1, 1024, 11, 2048, 0);
    seg(13, d_w1, w_d1, 1024, 11, 2048, 0);
    seg(14, e_w2, w_e2, 2048, 10, 1024, 0);
    seg(15, d_w2, w_d2, 2048, 10, 1024, 0);
    seg(16, depth, (uint32_t*)deph, NL * CH, 0, 1, 0);
    pack_w<<<dim3(256, 17), 256>>>(pk);

    const dim3 blk(256);
    const dim3 gblk(128);
    const dim3 gU(CH / 128, NL / 128);
    const dim3 gF(2 * CH / 128, NL / 128);
    const dim3 gQKV(3 * CH / 128, NL / 128);

    auto attention = [&](const __half* qp, int ldq, const __half* kp, const __half* vp, int ldkv) {
        attn_kv_h<<<dim3(NHT, KVSPLIT), gblk>>>(kp, vp, ldkv, kvp, ksp);
        kv_reduce_h<<<(NHT * (HD / 2) * HD + 255) / 256, blk>>>(kvp, kvh);
        ks_reduce_kernel<<<NHT, 128>>>(ksp, ks);
        attn_out_h<<<dim3(LQ / 128, NHT), gblk>>>(qp, ldq, kvh, ks, attnh);
    };

    // ===== encoder =====
    add_kernel<<<2048, blk>>>(context, pos, ctx, ctxh, NL * CH / 4);
    gemm_h<false, 2><<<gQKV, gblk, GEMM_SMEM2>>>((const uint32_t*)ctxh, w_qkvE, qkvh, NL, 512, 3 * CH);
    attention(qkvh, 3 * CH, qkvh + CH, qkvh + 2 * CH, 3 * CH);
    gemm_h<false, 0><<<gU, gblk, GEMM_SMEM2>>>((const uint32_t*)attnh, w_em, msg, NL, 512, CH);
    ln_res_kernel<<<NL, blk>>>(ctx, msg, e_g1, e_b1, x, xh);
    gemm_h<true, 2><<<gF, gblk, GEMM_SMEM2>>>((const uint32_t*)xh, w_e1, hh, NL, 512, 2 * CH);
    gemm_h<false, 0><<<gU, gblk, GEMM_SMEM2>>>((const uint32_t*)hh, w_e2, msg, NL, 1024, CH);
    ln_res_kernel<<<NL, blk>>>(x, msg, e_g2, e_b2, ctx, ctxh);

    // ===== decoder: self-attention =====
    gemm_h<false, 2><<<gQKV, gblk, GEMM_SMEM2>>>((const uint32_t*)deph, w_qkvD, qkvh, NL, 512, 3 * CH);
    attention(qkvh, 3 * CH, qkvh + CH, qkvh + 2 * CH, 3 * CH);
    gemm_h<false, 0><<<gU, gblk, GEMM_SMEM2>>>((const uint32_t*)attnh, w_dm0, msg, NL, 512, CH);
    ln_res_kernel<<<NL, blk>>>(depth, msg, d_g0, d_b0, x, xh);

    // ===== decoder: cross-attention =====
    {
        __half* crossq = qkvh;
        __half* crosskv = qkvh + (size_t)NL * CH;
        gemm_h<false, 2><<<gU, gblk, GEMM_SMEM2>>>((const uint32_t*)xh, w_q1, crossq, NL, 512, CH);
        gemm_h<false, 2><<<gF, gblk, GEMM_SMEM2>>>((const uint32_t*)ctxh, w_kvD1, crosskv, NL, 512, 2 * CH);
        attention(crossq, CH, crosskv, crosskv + CH, 2 * CH);
    }
    gemm_h<false, 0><<<gU, gblk, GEMM_SMEM2>>>((const uint32_t*)attnh, w_dm1, msg, NL, 512, CH);
    ln_res_kernel<<<NL, blk>>>(x, msg, d_g1, d_b1, yb, ybh);

    // ===== decoder: FFN =====
    gemm_h<true, 2><<<gF, gblk, GEMM_SMEM2>>>((const uint32_t*)ybh, w_d1, hh, NL, 512, 2 * CH);
    gemm_h<false, 0><<<gU, gblk, GEMM_SMEM2>>>((const uint32_t*)hh, w_d2, msg, NL, 1024, CH);
    ln_res_kernel<<<NL, blk>>>(yb, msg, d_g2, d_b2, out, nullptr);
}